// round 2
// baseline (speedup 1.0000x reference)
#include <cuda_runtime.h>

// GumbelSoftmaxVectorQuantizer — round 2
//
// K1: fp32 SGEMM 128x128x16 using packed fma.rn.f32x2 (FFMA2, sm_103a) —
//     2 fp32 FMAs per issued instruction, exact fp32 semantics.
//     Epilogue: (acc + b + gumbel) / TAU -> 256MB __device__ scratch.
// K2: unchanged softmax/argmax/gather kernel (HBM-bound, ~91us).

static constexpr int Mx = 16384;   // B*T
static constexpr int Kx = 1024;    // Din
static constexpr int Nx = 4096;    // G*V
static constexpr int Gx = 4;
static constexpr int Vx = 1024;
static constexpr int Dx = 128;
static constexpr float INV_TAU = 0.5f;   // TAU = 2.0

__device__ float g_logits[(size_t)Mx * Nx];

using ull = unsigned long long;

__device__ __forceinline__ ull pack_dup(float x) {
    ull r;
    asm("mov.b64 %0, {%1, %1};" : "=l"(r) : "f"(x));
    return r;
}

__device__ __forceinline__ void ffma2(ull& d, ull a, ull b) {
    asm("fma.rn.f32x2 %0, %1, %2, %0;" : "+l"(d) : "l"(a), "l"(b));
}

__device__ __forceinline__ void unpack2(ull v, float& lo, float& hi) {
    asm("mov.b64 {%0, %1}, %2;" : "=f"(lo), "=f"(hi) : "l"(v));
}

__global__ __launch_bounds__(256, 2)
void gemm_epilogue_kernel(const float* __restrict__ A,      // [M,K] inputs
                          const float* __restrict__ W,      // [K,N]
                          const float* __restrict__ bias,   // [N]
                          const float* __restrict__ gum)    // [M,N]
{
    __shared__ float As[2][16][132];   // [buf][k][m], padded rows
    __shared__ float Bs[2][16][128];   // [buf][k][n]

    const int tid  = threadIdx.x;
    const int bm   = blockIdx.y * 128;
    const int bn   = blockIdx.x * 128;

    // global->smem load mapping
    const int arow = tid >> 2;           // 0..63 (and +64)
    const int ak   = (tid & 3) << 2;     // k offset 0,4,8,12
    const int brow = tid >> 5;           // 0..7 (and +8)
    const int bcol = (tid & 31) << 2;    // 0..124

    // compute mapping: 16x16 threads, 8x8 micro-tile each
    const int row0 = (tid >> 4) << 3;
    const int col0 = (tid & 15) << 3;

    const float* Ab = A + (size_t)bm * Kx;

    // accumulators: 8 rows x 4 packed pairs (j pairs) = 64 fp32 values
    ull acc[8][4];
#pragma unroll
    for (int i = 0; i < 8; i++)
#pragma unroll
        for (int m = 0; m < 4; m++) acc[i][m] = 0ull;   // {0.f, 0.f}

    // prologue: tile 0
    {
        float4 a0 = *(const float4*)&Ab[(size_t)arow        * Kx + ak];
        float4 a1 = *(const float4*)&Ab[(size_t)(arow + 64) * Kx + ak];
        float4 b0 = *(const float4*)&W[(size_t)brow       * Nx + bn + bcol];
        float4 b1 = *(const float4*)&W[(size_t)(brow + 8) * Nx + bn + bcol];
        As[0][ak + 0][arow] = a0.x; As[0][ak + 1][arow] = a0.y;
        As[0][ak + 2][arow] = a0.z; As[0][ak + 3][arow] = a0.w;
        As[0][ak + 0][arow + 64] = a1.x; As[0][ak + 1][arow + 64] = a1.y;
        As[0][ak + 2][arow + 64] = a1.z; As[0][ak + 3][arow + 64] = a1.w;
        *(float4*)&Bs[0][brow][bcol]     = b0;
        *(float4*)&Bs[0][brow + 8][bcol] = b1;
    }
    __syncthreads();

    int buf = 0;
#pragma unroll 1
    for (int kt = 0; kt < Kx; kt += 16) {
        float4 a0n, a1n, b0n, b1n;
        const bool has = (kt + 16) < Kx;
        if (has) {
            const int k2 = kt + 16;
            a0n = *(const float4*)&Ab[(size_t)arow        * Kx + k2 + ak];
            a1n = *(const float4*)&Ab[(size_t)(arow + 64) * Kx + k2 + ak];
            b0n = *(const float4*)&W[(size_t)(k2 + brow)     * Nx + bn + bcol];
            b1n = *(const float4*)&W[(size_t)(k2 + brow + 8) * Nx + bn + bcol];
        }

#pragma unroll
        for (int kk = 0; kk < 16; kk++) {
            float a[8];
            *(float4*)&a[0] = *(const float4*)&As[buf][kk][row0];
            *(float4*)&a[4] = *(const float4*)&As[buf][kk][row0 + 4];
            // b pairs load natively as 64-bit lanes from smem
            longlong2 bq0 = *(const longlong2*)&Bs[buf][kk][col0];
            longlong2 bq1 = *(const longlong2*)&Bs[buf][kk][col0 + 4];
            ull bb[4];
            bb[0] = (ull)bq0.x; bb[1] = (ull)bq0.y;
            bb[2] = (ull)bq1.x; bb[3] = (ull)bq1.y;
#pragma unroll
            for (int i = 0; i < 8; i++) {
                const ull aa = pack_dup(a[i]);
#pragma unroll
                for (int m = 0; m < 4; m++)
                    ffma2(acc[i][m], aa, bb[m]);
            }
        }

        if (has) {
            buf ^= 1;
            As[buf][ak + 0][arow] = a0n.x; As[buf][ak + 1][arow] = a0n.y;
            As[buf][ak + 2][arow] = a0n.z; As[buf][ak + 3][arow] = a0n.w;
            As[buf][ak + 0][arow + 64] = a1n.x; As[buf][ak + 1][arow + 64] = a1n.y;
            As[buf][ak + 2][arow + 64] = a1n.z; As[buf][ak + 3][arow + 64] = a1n.w;
            *(float4*)&Bs[buf][brow][bcol]     = b0n;
            *(float4*)&Bs[buf][brow + 8][bcol] = b1n;
            __syncthreads();
        }
    }

    // epilogue: + bias + gumbel, * 1/TAU, write scratch
    float bc[8];
    *(float4*)&bc[0] = *(const float4*)&bias[bn + col0];
    *(float4*)&bc[4] = *(const float4*)&bias[bn + col0 + 4];

#pragma unroll
    for (int i = 0; i < 8; i++) {
        const size_t base = (size_t)(bm + row0 + i) * Nx + bn + col0;
        float4 g0 = *(const float4*)&gum[base];
        float4 g1 = *(const float4*)&gum[base + 4];
        float c[8];
#pragma unroll
        for (int m = 0; m < 4; m++) unpack2(acc[i][m], c[2 * m], c[2 * m + 1]);
        float4 o0, o1;
        o0.x = (c[0] + bc[0] + g0.x) * INV_TAU;
        o0.y = (c[1] + bc[1] + g0.y) * INV_TAU;
        o0.z = (c[2] + bc[2] + g0.z) * INV_TAU;
        o0.w = (c[3] + bc[3] + g0.w) * INV_TAU;
        o1.x = (c[4] + bc[4] + g1.x) * INV_TAU;
        o1.y = (c[5] + bc[5] + g1.y) * INV_TAU;
        o1.z = (c[6] + bc[6] + g1.z) * INV_TAU;
        o1.w = (c[7] + bc[7] + g1.w) * INV_TAU;
        *(float4*)&g_logits[base]     = o0;
        *(float4*)&g_logits[base + 4] = o1;
    }
}

__global__ __launch_bounds__(128)
void softmax_kernel(const int*   __restrict__ pads,       // [M] (B*T)
                    const float* __restrict__ codebook,   // [G,V,D]
                    float*       __restrict__ ids_out,    // [M*G]
                    float*       __restrict__ quant_out,  // [M, G*D]
                    float*       __restrict__ probs_out)  // [M*G, V]
{
    const int grp  = blockIdx.x;       // row*G + g
    const int row  = grp >> 2;
    const int g    = grp & 3;
    const int tid  = threadIdx.x;
    const int lane = tid & 31;
    const int warp = tid >> 5;

    const float* base = g_logits + (size_t)grp * Vx;

    float v[8];
    *(float4*)&v[0] = *(const float4*)&base[tid * 8];
    *(float4*)&v[4] = *(const float4*)&base[tid * 8 + 4];

    // local max + first-occurrence argmax
    float m = v[0]; int mi = tid * 8;
#pragma unroll
    for (int j = 1; j < 8; j++)
        if (v[j] > m) { m = v[j]; mi = tid * 8 + j; }

#pragma unroll
    for (int off = 16; off > 0; off >>= 1) {
        float om = __shfl_down_sync(0xffffffffu, m, off);
        int   oi = __shfl_down_sync(0xffffffffu, mi, off);
        if (om > m || (om == m && oi < mi)) { m = om; mi = oi; }
    }

    __shared__ float swarp[4];
    __shared__ int   sidx[4];
    __shared__ float red_m;
    __shared__ int   red_i;
    __shared__ float red_s;

    if (lane == 0) { swarp[warp] = m; sidx[warp] = mi; }
    __syncthreads();
    if (tid == 0) {
        float bmv = swarp[0]; int bi = sidx[0];
        for (int w = 1; w < 4; w++)
            if (swarp[w] > bmv || (swarp[w] == bmv && sidx[w] < bi)) {
                bmv = swarp[w]; bi = sidx[w];
            }
        red_m = bmv; red_i = bi;
    }
    __syncthreads();
    const float mx = red_m;

    float e[8]; float s = 0.f;
#pragma unroll
    for (int j = 0; j < 8; j++) { e[j] = __expf(v[j] - mx); s += e[j]; }
#pragma unroll
    for (int off = 16; off > 0; off >>= 1)
        s += __shfl_down_sync(0xffffffffu, s, off);
    if (lane == 0) swarp[warp] = s;
    __syncthreads();
    if (tid == 0) red_s = swarp[0] + swarp[1] + swarp[2] + swarp[3];
    __syncthreads();

    const int   pad = pads[row];
    const float inv = pad ? 0.f : (1.f / red_s);

    float4 p0, p1;
    p0.x = e[0] * inv; p0.y = e[1] * inv; p0.z = e[2] * inv; p0.w = e[3] * inv;
    p1.x = e[4] * inv; p1.y = e[5] * inv; p1.z = e[6] * inv; p1.w = e[7] * inv;
    *(float4*)&probs_out[(size_t)grp * Vx + tid * 8]     = p0;
    *(float4*)&probs_out[(size_t)grp * Vx + tid * 8 + 4] = p1;

    const int id = red_i;
    const float q = pad ? 0.f : codebook[(((g << 10) + id) << 7) + tid];
    quant_out[(size_t)row * (Gx * Dx) + g * Dx + tid] = q;

    if (tid == 0) ids_out[grp] = pad ? -1.0f : (float)id;
}

extern "C" void kernel_launch(void* const* d_in, const int* in_sizes, int n_in,
                              void* d_out, int out_size)
{
    const float* inputs = (const float*)d_in[0];   // (B,T,Din)
    const int*   pads   = (const int*)  d_in[1];   // (B,T)
    const float* gum    = (const float*)d_in[2];   // (B,T,G,V)
    const float* W      = (const float*)d_in[3];   // (Din, G*V)
    const float* bias   = (const float*)d_in[4];   // (G*V,)
    const float* cb     = (const float*)d_in[5];   // (G,V,D)

    float* out       = (float*)d_out;
    float* ids_out   = out;                                    // M*G
    float* quant_out = out + (size_t)Mx * Gx;                  // M*G*D
    float* probs_out = quant_out + (size_t)Mx * Gx * Dx;       // M*G*V

    dim3 grid(Nx / 128, Mx / 128);
    gemm_epilogue_kernel<<<grid, 256>>>(inputs, W, bias, gum);
    softmax_kernel<<<Mx * Gx, 128>>>(pads, cb, ids_out, quant_out, probs_out);
}

// round 5
// speedup vs baseline: 1.7858x; 1.7858x over previous
#include <cuda_runtime.h>
#include <cuda_bf16.h>
#include <cstdint>

// GumbelSoftmaxVectorQuantizer — round 5: mma.sync bf16x3 GEMM
// (tcgen05 unavailable: harness emits compute_103 PTX, no 'a' features)
//
// K0a: split A (fp32->bf16 hi/lo), row-major [M][K]
// K0b: split+transpose W -> [N][K] bf16 hi/lo
// K1 : mma.sync.m16n8k16 GEMM, 128x128x32 tiles, 4-stage cp.async,
//      D = Ah*Bh + Ah*Bl + Al*Bh (fp32 accum), epilogue (+b+gum)*0.5
// K2 : softmax/argmax top-2 + exact fp32 recompute of near ties.

static constexpr int Mx = 16384;
static constexpr int Kx = 1024;
static constexpr int Nx = 4096;
static constexpr int Vx = 1024;
static constexpr int Dx = 128;
static constexpr float INV_TAU = 0.5f;

__device__ float g_logits[(size_t)Mx * Nx];
__device__ unsigned short g_Ah[(size_t)Mx * Kx];   // [M][K]
__device__ unsigned short g_Al[(size_t)Mx * Kx];
__device__ unsigned short g_Bh[(size_t)Nx * Kx];   // [N][K] = W^T
__device__ unsigned short g_Bl[(size_t)Nx * Kx];

__device__ __forceinline__ uint32_t smem_u32(const void* p) {
    uint32_t a;
    asm("{ .reg .u64 t; cvta.to.shared.u64 t, %1; cvt.u32.u64 %0, t; }" : "=r"(a) : "l"(p));
    return a;
}

// ---------------- K0a: split A ----------------
__global__ __launch_bounds__(256)
void split_a_kernel(const float* __restrict__ A) {
    const size_t idx = ((size_t)blockIdx.x * 256 + threadIdx.x) * 8;
    if (idx >= (size_t)Mx * Kx) return;
    float4 a0 = *(const float4*)&A[idx];
    float4 a1 = *(const float4*)&A[idx + 4];
    float v[8] = {a0.x, a0.y, a0.z, a0.w, a1.x, a1.y, a1.z, a1.w};
    unsigned short h[8], l[8];
#pragma unroll
    for (int t = 0; t < 8; t++) {
        __nv_bfloat16 hb = __float2bfloat16(v[t]);
        h[t] = __bfloat16_as_ushort(hb);
        l[t] = __bfloat16_as_ushort(__float2bfloat16(v[t] - __bfloat162float(hb)));
    }
    uint4 uh, ul;
    uh.x = h[0] | ((uint32_t)h[1] << 16); uh.y = h[2] | ((uint32_t)h[3] << 16);
    uh.z = h[4] | ((uint32_t)h[5] << 16); uh.w = h[6] | ((uint32_t)h[7] << 16);
    ul.x = l[0] | ((uint32_t)l[1] << 16); ul.y = l[2] | ((uint32_t)l[3] << 16);
    ul.z = l[4] | ((uint32_t)l[5] << 16); ul.w = l[6] | ((uint32_t)l[7] << 16);
    *(uint4*)&g_Ah[idx] = uh;
    *(uint4*)&g_Al[idx] = ul;
}

// ---------------- K0b: split + transpose W ----------------
__global__ __launch_bounds__(256)
void split_w_kernel(const float* __restrict__ W) {
    __shared__ float s[64][65];
    const int ct = blockIdx.y;            // k tile
    const int n0 = blockIdx.x * 64;       // n tile
    const int k0 = ct * 64;
    const int tid = threadIdx.x;
    for (int i = tid; i < 1024; i += 256) {
        const int kk = i >> 4, n4 = (i & 15) << 2;
        float4 w = *(const float4*)&W[(size_t)(k0 + kk) * Nx + n0 + n4];
        s[kk][n4] = w.x; s[kk][n4 + 1] = w.y; s[kk][n4 + 2] = w.z; s[kk][n4 + 3] = w.w;
    }
    __syncthreads();
    for (int i = tid; i < 512; i += 256) {
        const int nl = i >> 3, j = (i & 7) << 3;
        unsigned short h[8], l[8];
#pragma unroll
        for (int t = 0; t < 8; t++) {
            float a = s[j + t][nl];
            __nv_bfloat16 hb = __float2bfloat16(a);
            h[t] = __bfloat16_as_ushort(hb);
            l[t] = __bfloat16_as_ushort(__float2bfloat16(a - __bfloat162float(hb)));
        }
        const size_t o = (size_t)(n0 + nl) * Kx + k0 + j;
        uint4 uh, ul;
        uh.x = h[0] | ((uint32_t)h[1] << 16); uh.y = h[2] | ((uint32_t)h[3] << 16);
        uh.z = h[4] | ((uint32_t)h[5] << 16); uh.w = h[6] | ((uint32_t)h[7] << 16);
        ul.x = l[0] | ((uint32_t)l[1] << 16); ul.y = l[2] | ((uint32_t)l[3] << 16);
        ul.z = l[4] | ((uint32_t)l[5] << 16); ul.w = l[6] | ((uint32_t)l[7] << 16);
        *(uint4*)&g_Bh[o] = uh;
        *(uint4*)&g_Bl[o] = ul;
    }
}

// ---------------- K1: mma.sync GEMM ----------------
static constexpr int BK = 32;
static constexpr int STAGES = 4;
static constexpr int RSTRIDE = 40;                 // bf16 elems per smem row
static constexpr int OP_ELEMS = 128 * RSTRIDE;     // 5120
static constexpr int STAGE_ELEMS = 4 * OP_ELEMS;   // 20480
static constexpr int SMEM_BYTES = STAGES * STAGE_ELEMS * 2;  // 163840
static constexpr int NCHUNK = Kx / BK;             // 32

__device__ __forceinline__ void cp16(uint32_t dst, const void* src) {
    asm volatile("cp.async.cg.shared.global [%0], [%1], 16;" :: "r"(dst), "l"(src) : "memory");
}
__device__ __forceinline__ void cp_commit() {
    asm volatile("cp.async.commit_group;" ::: "memory");
}
__device__ __forceinline__ void cp_wait2() {
    asm volatile("cp.async.wait_group 2;" ::: "memory");
}
__device__ __forceinline__ void ldsm4(uint32_t& r0, uint32_t& r1, uint32_t& r2, uint32_t& r3,
                                      uint32_t addr) {
    asm volatile("ldmatrix.sync.aligned.m8n8.x4.shared.b16 {%0,%1,%2,%3}, [%4];"
                 : "=r"(r0), "=r"(r1), "=r"(r2), "=r"(r3) : "r"(addr));
}
__device__ __forceinline__ void mma16816(float* c, const uint32_t* a, const uint32_t* b) {
    asm volatile(
        "mma.sync.aligned.m16n8k16.row.col.f32.bf16.bf16.f32 "
        "{%0,%1,%2,%3}, {%4,%5,%6,%7}, {%8,%9}, {%0,%1,%2,%3};"
        : "+f"(c[0]), "+f"(c[1]), "+f"(c[2]), "+f"(c[3])
        : "r"(a[0]), "r"(a[1]), "r"(a[2]), "r"(a[3]), "r"(b[0]), "r"(b[1]));
}

__global__ __launch_bounds__(256, 1)
void gemm_kernel(const float* __restrict__ bias, const float* __restrict__ gum) {
    extern __shared__ char smem[];
    const uint32_t sbase = smem_u32(smem);
    const int tid  = threadIdx.x;
    const int lane = tid & 31;
    const int wid  = tid >> 5;
    const int wm   = wid >> 2;          // 0..1
    const int wn   = wid & 3;           // 0..3
    const int bm   = blockIdx.y * 128;
    const int bn   = blockIdx.x * 128;

    // cp.async mapping: 2048 16B chunks per stage, 8 per thread
    // cidx: op = cidx>>9, r = (cidx>>2)&127, c = cidx&3
    const unsigned short* gsrc[4] = {
        g_Ah + (size_t)bm * Kx, g_Al + (size_t)bm * Kx,
        g_Bh + (size_t)bn * Kx, g_Bl + (size_t)bn * Kx };

    auto issue_stage = [&](int chunk) {
        const int s = chunk & (STAGES - 1);
        const int k0 = chunk * BK;
        const uint32_t stb = sbase + s * STAGE_ELEMS * 2;
#pragma unroll
        for (int it = 0; it < 8; it++) {
            const int cidx = tid + it * 256;
            const int op = cidx >> 9;
            const int r  = (cidx >> 2) & 127;
            const int c  = cidx & 3;
            const unsigned short* src = gsrc[op] + (size_t)r * Kx + k0 + c * 8;
            const uint32_t dst = stb + (op * OP_ELEMS + r * RSTRIDE + c * 8) * 2;
            cp16(dst, src);
        }
        cp_commit();
    };

    float acc[4][4][4];
#pragma unroll
    for (int i = 0; i < 4; i++)
#pragma unroll
        for (int j = 0; j < 4; j++)
#pragma unroll
            for (int q = 0; q < 4; q++) acc[i][j][q] = 0.f;

    issue_stage(0); issue_stage(1); issue_stage(2);

    const int lrow = lane & 15;
    const int lcol = (lane >> 4) * 8;

#pragma unroll 1
    for (int ch = 0; ch < NCHUNK; ch++) {
        cp_wait2();
        __syncthreads();
        if (ch + 3 < NCHUNK) issue_stage(ch + 3);

        const uint32_t stb = sbase + (ch & (STAGES - 1)) * STAGE_ELEMS * 2;
        const uint32_t aho = stb;
        const uint32_t alo = stb + OP_ELEMS * 2;
        const uint32_t bho = stb + 2 * OP_ELEMS * 2;
        const uint32_t blo = stb + 3 * OP_ELEMS * 2;

#pragma unroll
        for (int ks = 0; ks < 2; ks++) {
            const int kk = ks * 16;
            uint32_t ah[4][4], al[4][4], bh[4][2], bl[4][2];
#pragma unroll
            for (int mf = 0; mf < 4; mf++) {
                const int row = wm * 64 + mf * 16 + lrow;
                const uint32_t off = (uint32_t)(row * RSTRIDE + kk + lcol) * 2;
                ldsm4(ah[mf][0], ah[mf][1], ah[mf][2], ah[mf][3], aho + off);
                ldsm4(al[mf][0], al[mf][1], al[mf][2], al[mf][3], alo + off);
            }
#pragma unroll
            for (int np = 0; np < 2; np++) {
                const int row = wn * 32 + np * 16 + lrow;
                const uint32_t off = (uint32_t)(row * RSTRIDE + kk + lcol) * 2;
                uint32_t r0, r1, r2, r3;
                ldsm4(r0, r1, r2, r3, bho + off);
                bh[2 * np][0] = r0; bh[2 * np][1] = r2;
                bh[2 * np + 1][0] = r1; bh[2 * np + 1][1] = r3;
                ldsm4(r0, r1, r2, r3, blo + off);
                bl[2 * np][0] = r0; bl[2 * np][1] = r2;
                bl[2 * np + 1][0] = r1; bl[2 * np + 1][1] = r3;
            }
#pragma unroll
            for (int mf = 0; mf < 4; mf++)
#pragma unroll
                for (int nf = 0; nf < 4; nf++) {
                    mma16816(acc[mf][nf], ah[mf], bh[nf]);
                    mma16816(acc[mf][nf], ah[mf], bl[nf]);
                    mma16816(acc[mf][nf], al[mf], bh[nf]);
                }
        }
        __syncthreads();
    }

    // epilogue: (acc + bias + gumbel) * INV_TAU -> g_logits
    const int er = lane >> 2;
    const int ec = (lane & 3) * 2;
#pragma unroll
    for (int mf = 0; mf < 4; mf++) {
#pragma unroll
        for (int nf = 0; nf < 4; nf++) {
            const int col = bn + wn * 32 + nf * 8 + ec;
            const float2 bb = *(const float2*)&bias[col];
#pragma unroll
            for (int h = 0; h < 2; h++) {
                const int row = bm + wm * 64 + mf * 16 + er + h * 8;
                const size_t go = (size_t)row * Nx + col;
                const float2 g = *(const float2*)&gum[go];
                float2 o;
                o.x = (acc[mf][nf][2 * h]     + bb.x + g.x) * INV_TAU;
                o.y = (acc[mf][nf][2 * h + 1] + bb.y + g.y) * INV_TAU;
                *(float2*)&g_logits[go] = o;
            }
        }
    }
}

// ---------------- K2: softmax + argmax(top2 + exact fixup) ----------------
__global__ __launch_bounds__(128)
void softmax_kernel(const int*   __restrict__ pads,
                    const float* __restrict__ codebook,
                    const float* __restrict__ A,
                    const float* __restrict__ W,
                    const float* __restrict__ bias,
                    const float* __restrict__ gum,
                    float*       __restrict__ ids_out,
                    float*       __restrict__ quant_out,
                    float*       __restrict__ probs_out)
{
    const int grp  = blockIdx.x;
    const int row  = grp >> 2;
    const int g    = grp & 3;
    const int tid  = threadIdx.x;
    const int lane = tid & 31;
    const int warp = tid >> 5;

    const float* base = g_logits + (size_t)grp * Vx;

    float v[8];
    *(float4*)&v[0] = *(const float4*)&base[tid * 8];
    *(float4*)&v[4] = *(const float4*)&base[tid * 8 + 4];

    float m1 = v[0], m2 = -3.4e38f;
    int i1 = tid * 8, i2 = -1;
#pragma unroll
    for (int j = 1; j < 8; j++) {
        const int ii = tid * 8 + j;
        if (v[j] > m1) { m2 = m1; i2 = i1; m1 = v[j]; i1 = ii; }
        else if (v[j] > m2) { m2 = v[j]; i2 = ii; }
    }
#pragma unroll
    for (int off = 16; off > 0; off >>= 1) {
        float o1 = __shfl_down_sync(0xffffffffu, m1, off);
        int   oi1 = __shfl_down_sync(0xffffffffu, i1, off);
        float o2 = __shfl_down_sync(0xffffffffu, m2, off);
        int   oi2 = __shfl_down_sync(0xffffffffu, i2, off);
        if (o1 > m1 || (o1 == m1 && oi1 < i1)) {
            float t2 = (m1 > o2 || (m1 == o2 && i1 < oi2)) ? m1 : o2;
            int   ti2 = (m1 > o2 || (m1 == o2 && i1 < oi2)) ? i1 : oi2;
            m1 = o1; i1 = oi1; m2 = t2; i2 = ti2;
        } else {
            if (o1 > m2 || (o1 == m2 && oi1 < i2)) { m2 = o1; i2 = oi1; }
        }
    }

    __shared__ float sw1[4], sw2[4], ssum[4];
    __shared__ int   si1[4], si2[4];
    __shared__ float red_m, red_s, sfix[2];
    __shared__ int   red_i, cand1, cand2, need_fix;

    if (lane == 0) { sw1[warp] = m1; si1[warp] = i1; sw2[warp] = m2; si2[warp] = i2; }
    __syncthreads();
    if (tid == 0) {
        float b1 = sw1[0], b2 = sw2[0]; int j1 = si1[0], j2 = si2[0];
        for (int w = 1; w < 4; w++) {
            float o1 = sw1[w], o2 = sw2[w]; int oi1 = si1[w], oi2 = si2[w];
            if (o1 > b1 || (o1 == b1 && oi1 < j1)) {
                float t2 = (b1 > o2 || (b1 == o2 && j1 < oi2)) ? b1 : o2;
                int   ti2 = (b1 > o2 || (b1 == o2 && j1 < oi2)) ? j1 : oi2;
                b1 = o1; j1 = oi1; b2 = t2; j2 = ti2;
            } else if (o1 > b2 || (o1 == b2 && oi1 < j2)) { b2 = o1; j2 = oi1; }
        }
        red_m = b1; red_i = j1; cand1 = j1; cand2 = j2;
        need_fix = (b1 - b2 < 1e-3f) ? 1 : 0;
    }
    __syncthreads();

    const int pad = pads[row];

    if (need_fix && !pad) {
        const float* arow = A + (size_t)row * Kx;
        for (int cidx = 0; cidx < 2; cidx++) {
            const int vv = (cidx == 0) ? cand1 : cand2;
            const int col = (g << 10) + vv;
            float part = 0.f;
#pragma unroll
            for (int j = 0; j < 8; j++) {
                const int k = tid * 8 + j;
                part = fmaf(arow[k], W[(size_t)k * Nx + col], part);
            }
#pragma unroll
            for (int off = 16; off > 0; off >>= 1)
                part += __shfl_down_sync(0xffffffffu, part, off);
            if (lane == 0) ssum[warp] = part;
            __syncthreads();
            if (tid == 0) {
                float tot = ssum[0] + ssum[1] + ssum[2] + ssum[3];
                sfix[cidx] = (tot + bias[col] + gum[(size_t)grp * Vx + vv]) * INV_TAU;
            }
            __syncthreads();
        }
        if (tid == 0) {
            const float v1 = sfix[0], v2 = sfix[1];
            red_i = (v2 > v1 || (v2 == v1 && cand2 < cand1)) ? cand2 : cand1;
        }
        __syncthreads();
    }

    const float mx = red_m;
    float e[8]; float s = 0.f;
#pragma unroll
    for (int j = 0; j < 8; j++) { e[j] = __expf(v[j] - mx); s += e[j]; }
#pragma unroll
    for (int off = 16; off > 0; off >>= 1)
        s += __shfl_down_sync(0xffffffffu, s, off);
    if (lane == 0) ssum[warp] = s;
    __syncthreads();
    if (tid == 0) red_s = ssum[0] + ssum[1] + ssum[2] + ssum[3];
    __syncthreads();

    const float inv = pad ? 0.f : (1.f / red_s);
    float4 p0, p1;
    p0.x = e[0] * inv; p0.y = e[1] * inv; p0.z = e[2] * inv; p0.w = e[3] * inv;
    p1.x = e[4] * inv; p1.y = e[5] * inv; p1.z = e[6] * inv; p1.w = e[7] * inv;
    *(float4*)&probs_out[(size_t)grp * Vx + tid * 8]     = p0;
    *(float4*)&probs_out[(size_t)grp * Vx + tid * 8 + 4] = p1;

    const int id = red_i;
    const float q = pad ? 0.f : codebook[(((g << 10) + id) << 7) + tid];
    quant_out[(size_t)row * (4 * Dx) + g * Dx + tid] = q;
    if (tid == 0) ids_out[grp] = pad ? -1.0f : (float)id;
}

// ---------------- launch ----------------
extern "C" void kernel_launch(void* const* d_in, const int* in_sizes, int n_in,
                              void* d_out, int out_size)
{
    const float* inputs = (const float*)d_in[0];
    const int*   pads   = (const int*)  d_in[1];
    const float* gum    = (const float*)d_in[2];
    const float* W      = (const float*)d_in[3];
    const float* bias   = (const float*)d_in[4];
    const float* cb     = (const float*)d_in[5];

    float* out       = (float*)d_out;
    float* ids_out   = out;
    float* quant_out = out + (size_t)Mx * 4;
    float* probs_out = quant_out + (size_t)Mx * 4 * Dx;

    cudaFuncSetAttribute(gemm_kernel, cudaFuncAttributeMaxDynamicSharedMemorySize, SMEM_BYTES);

    split_a_kernel<<<(Mx * Kx / 8 + 255) / 256, 256>>>(inputs);
    dim3 wg(Nx / 64, Kx / 64);
    split_w_kernel<<<wg, 256>>>(W);
    dim3 grid(Nx / 128, Mx / 128);
    gemm_kernel<<<grid, 256, SMEM_BYTES>>>(bias, gum);
    softmax_kernel<<<Mx * 4, 128>>>(pads, cb, inputs, W, bias, gum,
                                    ids_out, quant_out, probs_out);
}

// round 6
// speedup vs baseline: 1.8555x; 1.0390x over previous
#include <cuda_runtime.h>
#include <cuda_bf16.h>
#include <cstdint>

// GumbelSoftmaxVectorQuantizer — round 6: mma.sync bf16x3 GEMM, stall fixes
//   * 512-thread CTA (16 warps, 4/SMSP) for latency hiding
//   * product loop outermost -> no 3-deep accumulator RAW chains
//   * compile-time cp.async operand mapping (no local-mem pointer array)

static constexpr int Mx = 16384;
static constexpr int Kx = 1024;
static constexpr int Nx = 4096;
static constexpr int Vx = 1024;
static constexpr int Dx = 128;
static constexpr float INV_TAU = 0.5f;

__device__ float g_logits[(size_t)Mx * Nx];
__device__ unsigned short g_Ah[(size_t)Mx * Kx];   // [M][K]
__device__ unsigned short g_Al[(size_t)Mx * Kx];
__device__ unsigned short g_Bh[(size_t)Nx * Kx];   // [N][K] = W^T
__device__ unsigned short g_Bl[(size_t)Nx * Kx];

__device__ __forceinline__ uint32_t smem_u32(const void* p) {
    uint32_t a;
    asm("{ .reg .u64 t; cvta.to.shared.u64 t, %1; cvt.u32.u64 %0, t; }" : "=r"(a) : "l"(p));
    return a;
}

// ---------------- K0a: split A ----------------
__global__ __launch_bounds__(256)
void split_a_kernel(const float* __restrict__ A) {
    const size_t idx = ((size_t)blockIdx.x * 256 + threadIdx.x) * 8;
    if (idx >= (size_t)Mx * Kx) return;
    float4 a0 = *(const float4*)&A[idx];
    float4 a1 = *(const float4*)&A[idx + 4];
    float v[8] = {a0.x, a0.y, a0.z, a0.w, a1.x, a1.y, a1.z, a1.w};
    unsigned short h[8], l[8];
#pragma unroll
    for (int t = 0; t < 8; t++) {
        __nv_bfloat16 hb = __float2bfloat16(v[t]);
        h[t] = __bfloat16_as_ushort(hb);
        l[t] = __bfloat16_as_ushort(__float2bfloat16(v[t] - __bfloat162float(hb)));
    }
    uint4 uh, ul;
    uh.x = h[0] | ((uint32_t)h[1] << 16); uh.y = h[2] | ((uint32_t)h[3] << 16);
    uh.z = h[4] | ((uint32_t)h[5] << 16); uh.w = h[6] | ((uint32_t)h[7] << 16);
    ul.x = l[0] | ((uint32_t)l[1] << 16); ul.y = l[2] | ((uint32_t)l[3] << 16);
    ul.z = l[4] | ((uint32_t)l[5] << 16); ul.w = l[6] | ((uint32_t)l[7] << 16);
    *(uint4*)&g_Ah[idx] = uh;
    *(uint4*)&g_Al[idx] = ul;
}

// ---------------- K0b: split + transpose W ----------------
__global__ __launch_bounds__(256)
void split_w_kernel(const float* __restrict__ W) {
    __shared__ float s[64][65];
    const int ct = blockIdx.y;
    const int n0 = blockIdx.x * 64;
    const int k0 = ct * 64;
    const int tid = threadIdx.x;
    for (int i = tid; i < 1024; i += 256) {
        const int kk = i >> 4, n4 = (i & 15) << 2;
        float4 w = *(const float4*)&W[(size_t)(k0 + kk) * Nx + n0 + n4];
        s[kk][n4] = w.x; s[kk][n4 + 1] = w.y; s[kk][n4 + 2] = w.z; s[kk][n4 + 3] = w.w;
    }
    __syncthreads();
    for (int i = tid; i < 512; i += 256) {
        const int nl = i >> 3, j = (i & 7) << 3;
        unsigned short h[8], l[8];
#pragma unroll
        for (int t = 0; t < 8; t++) {
            float a = s[j + t][nl];
            __nv_bfloat16 hb = __float2bfloat16(a);
            h[t] = __bfloat16_as_ushort(hb);
            l[t] = __bfloat16_as_ushort(__float2bfloat16(a - __bfloat162float(hb)));
        }
        const size_t o = (size_t)(n0 + nl) * Kx + k0 + j;
        uint4 uh, ul;
        uh.x = h[0] | ((uint32_t)h[1] << 16); uh.y = h[2] | ((uint32_t)h[3] << 16);
        uh.z = h[4] | ((uint32_t)h[5] << 16); uh.w = h[6] | ((uint32_t)h[7] << 16);
        ul.x = l[0] | ((uint32_t)l[1] << 16); ul.y = l[2] | ((uint32_t)l[3] << 16);
        ul.z = l[4] | ((uint32_t)l[5] << 16); ul.w = l[6] | ((uint32_t)l[7] << 16);
        *(uint4*)&g_Bh[o] = uh;
        *(uint4*)&g_Bl[o] = ul;
    }
}

// ---------------- K1: mma.sync GEMM ----------------
static constexpr int BK = 32;
static constexpr int STAGES = 4;
static constexpr int RSTRIDE = 40;                 // bf16 per smem row (80B)
static constexpr int OP_ELEMS = 128 * RSTRIDE;     // 5120
static constexpr int STAGE_ELEMS = 4 * OP_ELEMS;   // 20480
static constexpr int SMEM_BYTES = STAGES * STAGE_ELEMS * 2;  // 163840
static constexpr int NCHUNK = Kx / BK;             // 32
static constexpr int NTHREADS = 512;

__device__ __forceinline__ void cp16(uint32_t dst, const void* src) {
    asm volatile("cp.async.cg.shared.global [%0], [%1], 16;" :: "r"(dst), "l"(src) : "memory");
}
__device__ __forceinline__ void cp_commit() {
    asm volatile("cp.async.commit_group;" ::: "memory");
}
__device__ __forceinline__ void cp_wait2() {
    asm volatile("cp.async.wait_group 2;" ::: "memory");
}
__device__ __forceinline__ void ldsm4(uint32_t& r0, uint32_t& r1, uint32_t& r2, uint32_t& r3,
                                      uint32_t addr) {
    asm volatile("ldmatrix.sync.aligned.m8n8.x4.shared.b16 {%0,%1,%2,%3}, [%4];"
                 : "=r"(r0), "=r"(r1), "=r"(r2), "=r"(r3) : "r"(addr));
}
__device__ __forceinline__ void mma16816(float* c, const uint32_t* a, const uint32_t* b) {
    asm volatile(
        "mma.sync.aligned.m16n8k16.row.col.f32.bf16.bf16.f32 "
        "{%0,%1,%2,%3}, {%4,%5,%6,%7}, {%8,%9}, {%0,%1,%2,%3};"
        : "+f"(c[0]), "+f"(c[1]), "+f"(c[2]), "+f"(c[3])
        : "r"(a[0]), "r"(a[1]), "r"(a[2]), "r"(a[3]), "r"(b[0]), "r"(b[1]));
}

__global__ __launch_bounds__(NTHREADS, 1)
void gemm_kernel(const float* __restrict__ bias, const float* __restrict__ gum) {
    extern __shared__ char smem[];
    const uint32_t sbase = smem_u32(smem);
    const int tid  = threadIdx.x;
    const int lane = tid & 31;
    const int wid  = tid >> 5;          // 0..15
    const int wm   = wid >> 2;          // 0..3 : 32-row slice
    const int wn   = wid & 3;           // 0..3 : 32-col slice
    const int bm   = blockIdx.y * 128;
    const int bn   = blockIdx.x * 128;

    const unsigned short* srcAh = g_Ah + (size_t)bm * Kx;
    const unsigned short* srcAl = g_Al + (size_t)bm * Kx;
    const unsigned short* srcBh = g_Bh + (size_t)bn * Kx;
    const unsigned short* srcBl = g_Bl + (size_t)bn * Kx;

    // 2048 x 16B per stage; 4 per thread; op index = it (compile-time)
    auto issue_stage = [&](int chunk) {
        const int s = chunk & (STAGES - 1);
        const int k0 = chunk * BK;
        const uint32_t stb = sbase + s * STAGE_ELEMS * 2;
        const int r = (tid >> 2) & 127;
        const int c = tid & 3;
        const uint32_t doff = (uint32_t)(r * RSTRIDE + c * 8) * 2;
        const size_t soff = (size_t)r * Kx + k0 + c * 8;
        cp16(stb + doff,                    srcAh + soff);
        cp16(stb + OP_ELEMS * 2 + doff,     srcAl + soff);
        cp16(stb + 2 * OP_ELEMS * 2 + doff, srcBh + soff);
        cp16(stb + 3 * OP_ELEMS * 2 + doff, srcBl + soff);
        cp_commit();
    };

    float acc[2][4][4];
#pragma unroll
    for (int i = 0; i < 2; i++)
#pragma unroll
        for (int j = 0; j < 4; j++)
#pragma unroll
            for (int q = 0; q < 4; q++) acc[i][j][q] = 0.f;

    issue_stage(0); issue_stage(1); issue_stage(2);

    const int lrow = lane & 15;
    const int lcol = (lane >> 4) * 8;

#pragma unroll 1
    for (int ch = 0; ch < NCHUNK; ch++) {
        cp_wait2();
        __syncthreads();
        if (ch + 3 < NCHUNK) issue_stage(ch + 3);

        const uint32_t stb = sbase + (ch & (STAGES - 1)) * STAGE_ELEMS * 2;
        const uint32_t aho = stb;
        const uint32_t alo = stb + OP_ELEMS * 2;
        const uint32_t bho = stb + 2 * OP_ELEMS * 2;
        const uint32_t blo = stb + 3 * OP_ELEMS * 2;

#pragma unroll
        for (int ks = 0; ks < 2; ks++) {
            const int kk = ks * 16;
            uint32_t ah[2][4], al[2][4], bh[4][2], bl[4][2];
#pragma unroll
            for (int mf = 0; mf < 2; mf++) {
                const int row = wm * 32 + mf * 16 + lrow;
                const uint32_t off = (uint32_t)(row * RSTRIDE + kk + lcol) * 2;
                ldsm4(ah[mf][0], ah[mf][1], ah[mf][2], ah[mf][3], aho + off);
                ldsm4(al[mf][0], al[mf][1], al[mf][2], al[mf][3], alo + off);
            }
#pragma unroll
            for (int np = 0; np < 2; np++) {
                const int row = wn * 32 + np * 16 + lrow;
                const uint32_t off = (uint32_t)(row * RSTRIDE + kk + lcol) * 2;
                uint32_t r0, r1, r2, r3;
                ldsm4(r0, r1, r2, r3, bho + off);
                bh[2 * np][0] = r0; bh[2 * np][1] = r2;
                bh[2 * np + 1][0] = r1; bh[2 * np + 1][1] = r3;
                ldsm4(r0, r1, r2, r3, blo + off);
                bl[2 * np][0] = r0; bl[2 * np][1] = r2;
                bl[2 * np + 1][0] = r1; bl[2 * np + 1][1] = r3;
            }
            // product loop OUTERMOST: consecutive MMAs hit distinct accumulators
#pragma unroll
            for (int mf = 0; mf < 2; mf++)
#pragma unroll
                for (int nf = 0; nf < 4; nf++)
                    mma16816(acc[mf][nf], ah[mf], bh[nf]);
#pragma unroll
            for (int mf = 0; mf < 2; mf++)
#pragma unroll
                for (int nf = 0; nf < 4; nf++)
                    mma16816(acc[mf][nf], ah[mf], bl[nf]);
#pragma unroll
            for (int mf = 0; mf < 2; mf++)
#pragma unroll
                for (int nf = 0; nf < 4; nf++)
                    mma16816(acc[mf][nf], al[mf], bh[nf]);
        }
        __syncthreads();
    }

    // epilogue: (acc + bias + gumbel) * INV_TAU -> g_logits
    const int er = lane >> 2;
    const int ec = (lane & 3) * 2;
#pragma unroll
    for (int mf = 0; mf < 2; mf++) {
#pragma unroll
        for (int nf = 0; nf < 4; nf++) {
            const int col = bn + wn * 32 + nf * 8 + ec;
            const float2 bb = *(const float2*)&bias[col];
#pragma unroll
            for (int h = 0; h < 2; h++) {
                const int row = bm + wm * 32 + mf * 16 + er + h * 8;
                const size_t go = (size_t)row * Nx + col;
                const float2 g = *(const float2*)&gum[go];
                float2 o;
                o.x = (acc[mf][nf][2 * h]     + bb.x + g.x) * INV_TAU;
                o.y = (acc[mf][nf][2 * h + 1] + bb.y + g.y) * INV_TAU;
                *(float2*)&g_logits[go] = o;
            }
        }
    }
}

// ---------------- K2: softmax + argmax(top2 + exact fixup) ----------------
__global__ __launch_bounds__(128)
void softmax_kernel(const int*   __restrict__ pads,
                    const float* __restrict__ codebook,
                    const float* __restrict__ A,
                    const float* __restrict__ W,
                    const float* __restrict__ bias,
                    const float* __restrict__ gum,
                    float*       __restrict__ ids_out,
                    float*       __restrict__ quant_out,
                    float*       __restrict__ probs_out)
{
    const int grp  = blockIdx.x;
    const int row  = grp >> 2;
    const int g    = grp & 3;
    const int tid  = threadIdx.x;
    const int lane = tid & 31;
    const int warp = tid >> 5;

    const float* base = g_logits + (size_t)grp * Vx;

    float v[8];
    *(float4*)&v[0] = *(const float4*)&base[tid * 8];
    *(float4*)&v[4] = *(const float4*)&base[tid * 8 + 4];

    float m1 = v[0], m2 = -3.4e38f;
    int i1 = tid * 8, i2 = -1;
#pragma unroll
    for (int j = 1; j < 8; j++) {
        const int ii = tid * 8 + j;
        if (v[j] > m1) { m2 = m1; i2 = i1; m1 = v[j]; i1 = ii; }
        else if (v[j] > m2) { m2 = v[j]; i2 = ii; }
    }
#pragma unroll
    for (int off = 16; off > 0; off >>= 1) {
        float o1 = __shfl_down_sync(0xffffffffu, m1, off);
        int   oi1 = __shfl_down_sync(0xffffffffu, i1, off);
        float o2 = __shfl_down_sync(0xffffffffu, m2, off);
        int   oi2 = __shfl_down_sync(0xffffffffu, i2, off);
        if (o1 > m1 || (o1 == m1 && oi1 < i1)) {
            float t2 = (m1 > o2 || (m1 == o2 && i1 < oi2)) ? m1 : o2;
            int   ti2 = (m1 > o2 || (m1 == o2 && i1 < oi2)) ? i1 : oi2;
            m1 = o1; i1 = oi1; m2 = t2; i2 = ti2;
        } else {
            if (o1 > m2 || (o1 == m2 && oi1 < i2)) { m2 = o1; i2 = oi1; }
        }
    }

    __shared__ float sw1[4], sw2[4], ssum[4];
    __shared__ int   si1[4], si2[4];
    __shared__ float red_m, red_s, sfix[2];
    __shared__ int   red_i, cand1, cand2, need_fix;

    if (lane == 0) { sw1[warp] = m1; si1[warp] = i1; sw2[warp] = m2; si2[warp] = i2; }
    __syncthreads();
    if (tid == 0) {
        float b1 = sw1[0], b2 = sw2[0]; int j1 = si1[0], j2 = si2[0];
        for (int w = 1; w < 4; w++) {
            float o1 = sw1[w], o2 = sw2[w]; int oi1 = si1[w], oi2 = si2[w];
            if (o1 > b1 || (o1 == b1 && oi1 < j1)) {
                float t2 = (b1 > o2 || (b1 == o2 && j1 < oi2)) ? b1 : o2;
                int   ti2 = (b1 > o2 || (b1 == o2 && j1 < oi2)) ? j1 : oi2;
                b1 = o1; j1 = oi1; b2 = t2; j2 = ti2;
            } else if (o1 > b2 || (o1 == b2 && oi1 < j2)) { b2 = o1; j2 = oi1; }
        }
        red_m = b1; red_i = j1; cand1 = j1; cand2 = j2;
        need_fix = (b1 - b2 < 1e-3f) ? 1 : 0;
    }
    __syncthreads();

    const int pad = pads[row];

    if (need_fix && !pad) {
        const float* arow = A + (size_t)row * Kx;
        for (int cidx = 0; cidx < 2; cidx++) {
            const int vv = (cidx == 0) ? cand1 : cand2;
            const int col = (g << 10) + vv;
            float part = 0.f;
#pragma unroll
            for (int j = 0; j < 8; j++) {
                const int k = tid * 8 + j;
                part = fmaf(arow[k], W[(size_t)k * Nx + col], part);
            }
#pragma unroll
            for (int off = 16; off > 0; off >>= 1)
                part += __shfl_down_sync(0xffffffffu, part, off);
            if (lane == 0) ssum[warp] = part;
            __syncthreads();
            if (tid == 0) {
                float tot = ssum[0] + ssum[1] + ssum[2] + ssum[3];
                sfix[cidx] = (tot + bias[col] + gum[(size_t)grp * Vx + vv]) * INV_TAU;
            }
            __syncthreads();
        }
        if (tid == 0) {
            const float v1 = sfix[0], v2 = sfix[1];
            red_i = (v2 > v1 || (v2 == v1 && cand2 < cand1)) ? cand2 : cand1;
        }
        __syncthreads();
    }

    const float mx = red_m;
    float e[8]; float s = 0.f;
#pragma unroll
    for (int j = 0; j < 8; j++) { e[j] = __expf(v[j] - mx); s += e[j]; }
#pragma unroll
    for (int off = 16; off > 0; off >>= 1)
        s += __shfl_down_sync(0xffffffffu, s, off);
    if (lane == 0) ssum[warp] = s;
    __syncthreads();
    if (tid == 0) red_s = ssum[0] + ssum[1] + ssum[2] + ssum[3];
    __syncthreads();

    const float inv = pad ? 0.f : (1.f / red_s);
    float4 p0, p1;
    p0.x = e[0] * inv; p0.y = e[1] * inv; p0.z = e[2] * inv; p0.w = e[3] * inv;
    p1.x = e[4] * inv; p1.y = e[5] * inv; p1.z = e[6] * inv; p1.w = e[7] * inv;
    *(float4*)&probs_out[(size_t)grp * Vx + tid * 8]     = p0;
    *(float4*)&probs_out[(size_t)grp * Vx + tid * 8 + 4] = p1;

    const int id = red_i;
    const float q = pad ? 0.f : codebook[(((g << 10) + id) << 7) + tid];
    quant_out[(size_t)row * (4 * Dx) + g * Dx + tid] = q;
    if (tid == 0) ids_out[grp] = pad ? -1.0f : (float)id;
}

// ---------------- launch ----------------
extern "C" void kernel_launch(void* const* d_in, const int* in_sizes, int n_in,
                              void* d_out, int out_size)
{
    const float* inputs = (const float*)d_in[0];
    const int*   pads   = (const int*)  d_in[1];
    const float* gum    = (const float*)d_in[2];
    const float* W      = (const float*)d_in[3];
    const float* bias   = (const float*)d_in[4];
    const float* cb     = (const float*)d_in[5];

    float* out       = (float*)d_out;
    float* ids_out   = out;
    float* quant_out = out + (size_t)Mx * 4;
    float* probs_out = quant_out + (size_t)Mx * 4 * Dx;

    cudaFuncSetAttribute(gemm_kernel, cudaFuncAttributeMaxDynamicSharedMemorySize, SMEM_BYTES);

    split_a_kernel<<<(Mx * Kx / 8 + 255) / 256, 256>>>(inputs);
    dim3 wg(Nx / 64, Kx / 64);
    split_w_kernel<<<wg, 256>>>(W);
    dim3 grid(Nx / 128, Mx / 128);
    gemm_kernel<<<grid, NTHREADS, SMEM_BYTES>>>(bias, gum);
    softmax_kernel<<<Mx * 4, 128>>>(pads, cb, inputs, W, bias, gum,
                                    ids_out, quant_out, probs_out);
}